// round 14
// baseline (speedup 1.0000x reference)
#include <cuda_runtime.h>
#include <cuda_bf16.h>
#include <math.h>

// Problem constants
#define T_STEPS 2048
#define H_DIM   1024
#define G_DIM   4096   // 4*H
#define NCTA    128    // <= SM count -> co-resident (required for dataflow scan)
#define NPKT    512    // h packets per step (2 h values per 8B packet)
#define SENT32  0x7FC00000u   // NaN bits: never produced by finite LSTM math

typedef unsigned long long ull;

// ---------------- device scratch (static: no allocation allowed) ------------
__device__ float g_gx[(size_t)T_STEPS * G_DIM];       // 32 MB gate inputs
// per-step pair-packed h: packet p of step s = {h[2p], h[2p+1]} bits.
// Sentinel NaN means "not yet written" (8B store is atomic, so low-half check ok).
__device__ ull g_hpk[(size_t)(T_STEPS + 1) * NPKT];

// packed fp32x2 FMA (Blackwell FFMA2 — only reachable via PTX)
__device__ __forceinline__ ull fma2(ull a, ull b, ull c) {
    ull d;
    asm("fma.rn.f32x2 %0, %1, %2, %3;" : "=l"(d) : "l"(a), "l"(b), "l"(c));
    return d;
}
__device__ __forceinline__ ull pack2(float x, float y) {
    ull d;
    asm("mov.b64 %0, {%1, %2};" : "=l"(d) : "f"(x), "f"(y));
    return d;
}

// fast activations (validated R5/R11/R12)
__device__ __forceinline__ float sigmoid_fast(float x) {
    return 1.f / (1.f + __expf(-x));
}
__device__ __forceinline__ float tanh_fast(float x) {
    return 2.f / (1.f + __expf(-2.f * x)) - 1.f;
}

// ---------------- init: sentinel everywhere, h0 = 0 --------------------------
__global__ void init_kernel() {
    size_t i = (size_t)blockIdx.x * blockDim.x + threadIdx.x;
    size_t n = (size_t)(T_STEPS + 1) * NPKT;
    if (i < n) {
        g_hpk[i] = (i < NPKT) ? 0ull
                              : (((ull)SENT32 << 32) | (ull)SENT32);
    }
}

// ---------------- GEMM: gx[t][r] = dot(emb[tok[t]], W_ih[r]) + b ------------
// f32x2-packed inner loop (proven R6+). Unchanged from R12.
__global__ void __launch_bounds__(256) gemm_gx(
    const int* __restrict__ tokens, const float* __restrict__ emb,
    const float* __restrict__ Wih,  const float* __restrict__ bih,
    const float* __restrict__ bhh)
{
    __shared__ float As[16][128];
    __shared__ float Bs[16][128];
    __shared__ int   tok[128];

    const int tid = threadIdx.x;
    const int n0  = blockIdx.x * 128;
    const int m0  = blockIdx.y * 128;

    if (tid < 128) tok[tid] = tokens[m0 + tid];
    __syncthreads();

    const int trow = tid >> 4;
    const int tcol = tid & 15;
    const int lm   = tid >> 2;
    const int lk   = (tid & 3) << 2;

    ull acc2[8][4];
#pragma unroll
    for (int i = 0; i < 8; ++i)
#pragma unroll
        for (int jp = 0; jp < 4; ++jp) acc2[i][jp] = 0ull;

    for (int kt = 0; kt < H_DIM; kt += 16) {
#pragma unroll
        for (int r = 0; r < 2; ++r) {
            const int m = lm + r * 64;
            float4 v = *reinterpret_cast<const float4*>(
                emb + (size_t)tok[m] * H_DIM + kt + lk);
            As[lk + 0][m] = v.x; As[lk + 1][m] = v.y;
            As[lk + 2][m] = v.z; As[lk + 3][m] = v.w;
            float4 u = *reinterpret_cast<const float4*>(
                Wih + (size_t)(n0 + m) * H_DIM + kt + lk);
            Bs[lk + 0][m] = u.x; Bs[lk + 1][m] = u.y;
            Bs[lk + 2][m] = u.z; Bs[lk + 3][m] = u.w;
        }
        __syncthreads();

#pragma unroll
        for (int kk = 0; kk < 16; ++kk) {
            float a[8];
            float4 a0 = *reinterpret_cast<const float4*>(&As[kk][trow * 8]);
            float4 a1 = *reinterpret_cast<const float4*>(&As[kk][trow * 8 + 4]);
            a[0]=a0.x; a[1]=a0.y; a[2]=a0.z; a[3]=a0.w;
            a[4]=a1.x; a[5]=a1.y; a[6]=a1.z; a[7]=a1.w;
            const ull* bp = reinterpret_cast<const ull*>(&Bs[kk][tcol * 8]);
            ull b2[4] = {bp[0], bp[1], bp[2], bp[3]};
#pragma unroll
            for (int i = 0; i < 8; ++i) {
                ull ai = pack2(a[i], a[i]);
#pragma unroll
                for (int jp = 0; jp < 4; ++jp)
                    acc2[i][jp] = fma2(ai, b2[jp], acc2[i][jp]);
            }
        }
        __syncthreads();
    }

    float2 bias[4];
#pragma unroll
    for (int jp = 0; jp < 4; ++jp) {
        const int n = n0 + tcol * 8 + jp * 2;
        bias[jp].x = bih[n]     + bhh[n];
        bias[jp].y = bih[n + 1] + bhh[n + 1];
    }
#pragma unroll
    for (int i = 0; i < 8; ++i) {
        const int m = m0 + trow * 8 + i;
        float2* orow = reinterpret_cast<float2*>(
            g_gx + (size_t)m * G_DIM + n0 + tcol * 8);
#pragma unroll
        for (int jp = 0; jp < 4; ++jp) {
            float2 f = *reinterpret_cast<float2*>(&acc2[i][jp]);
            f.x += bias[jp].x;
            f.y += bias[jp].y;
            orow[jp] = f;
        }
    }
}

// ---------------- persistent LSTM scan (transposed dataflow) -----------------
// 128 CTAs x 512 threads. Thread tid polls ONE packet {h[2tid], h[2tid+1]}
// (its only h dependency -> no h staging, no sync1, R12-level poll traffic)
// and computes that k-pair's contribution to ALL 32 gate-rows of this CTA.
// Fold-transpose (31 shfls) leaves lane l holding the warp-sum of row l;
// 16 warps -> red[warp][row]; ONE syncthreads; warp 0 epilogue.
__global__ void __launch_bounds__(512, 1) lstm_scan(
    const float* __restrict__ Whh, float* __restrict__ out)
{
    const int tid  = threadIdx.x;
    const int b    = blockIdx.x;
    const int lane = tid & 31;
    const int wrp  = tid >> 5;        // 0..15

    // W pairs for all 32 rows at my k-pair column (64 regs):
    // row r = gate(r>>3), j(r&7); w2[r] = {W[grow][2*tid], W[grow][2*tid+1]}
    ull w2[32];
#pragma unroll
    for (int r = 0; r < 32; ++r) {
        const size_t grow = (size_t)((r >> 3) * H_DIM + (b << 3) + (r & 7));
        w2[r] = *reinterpret_cast<const ull*>(Whh + grow * H_DIM + 2 * tid);
    }

    __shared__ float red2[2][16][32];  // [step&1][warp][row]

    // epilogue mapping (warp 0): lane l -> row l (gate = l>>3, j = l&7)
    const int eg = lane >> 3;          // gate 0..3
    const int ej = lane & 7;           // row j 0..7
    const int ejg = (b << 3) + ej;     // global j
    float c = 0.f;                     // cell state lives in lanes 0..7

#pragma unroll 1
    for (int s = 0; s < T_STEPS; ++s) {
        // warp 0 prefetches gx for its (gate, j) (independent of h)
        float pg = 0.f;
        if (tid < 32) {
            pg = __ldg(g_gx + (size_t)s * G_DIM + eg * H_DIM + ejg);
        }

        // single scalar spin on my one packet (proven R12 handshake)
        ull h2;
        {
            const ull* src = g_hpk + (size_t)s * NPKT + tid;
            for (;;) {
                asm volatile("ld.global.cg.u64 %0, [%1];" : "=l"(h2) : "l"(src));
                if ((unsigned)h2 != SENT32) break;
                __nanosleep(24);
            }
        }
        // NO sync: compute starts the moment MY packet lands

        // 32 rows x 1 packed FMA + horizontal add
        float v[32];
#pragma unroll
        for (int r = 0; r < 32; ++r) {
            ull a = fma2(w2[r], h2, 0ull);
            float2 f = *reinterpret_cast<float2*>(&a);
            v[r] = f.x + f.y;
        }

        // fold-transpose: 31 shfls; lane l ends with warp-sum of row l
#pragma unroll
        for (int r = 0; r < 16; ++r) {
            float send = (lane & 16) ? v[r] : v[r + 16];
            float recv = __shfl_xor_sync(0xFFFFFFFFu, send, 16);
            v[r] = ((lane & 16) ? v[r + 16] : v[r]) + recv;
        }
#pragma unroll
        for (int r = 0; r < 8; ++r) {
            float send = (lane & 8) ? v[r] : v[r + 8];
            float recv = __shfl_xor_sync(0xFFFFFFFFu, send, 8);
            v[r] = ((lane & 8) ? v[r + 8] : v[r]) + recv;
        }
#pragma unroll
        for (int r = 0; r < 4; ++r) {
            float send = (lane & 4) ? v[r] : v[r + 4];
            float recv = __shfl_xor_sync(0xFFFFFFFFu, send, 4);
            v[r] = ((lane & 4) ? v[r + 4] : v[r]) + recv;
        }
#pragma unroll
        for (int r = 0; r < 2; ++r) {
            float send = (lane & 2) ? v[r] : v[r + 2];
            float recv = __shfl_xor_sync(0xFFFFFFFFu, send, 2);
            v[r] = ((lane & 2) ? v[r + 2] : v[r]) + recv;
        }
        {
            float send = (lane & 1) ? v[0] : v[1];
            float recv = __shfl_xor_sync(0xFFFFFFFFu, send, 1);
            v[0] = ((lane & 1) ? v[1] : v[0]) + recv;
        }
        red2[s & 1][wrp][lane] = v[0];
        __syncthreads();   // the ONE barrier: red2[s&1] complete before read.
                           // Cross-step reuse safe: red2[s&1] is rewritten at
                           // s+2 only after passing sync(s+1), which warp 0
                           // reaches only after reading red2[s&1] here.

        // epilogue: warp 0, lane l = row l; sum 16 warp partials (LDS tree)
        if (tid < 32) {
            float p0 = red2[s & 1][0][lane] + red2[s & 1][1][lane];
            float p1 = red2[s & 1][2][lane] + red2[s & 1][3][lane];
            float p2 = red2[s & 1][4][lane] + red2[s & 1][5][lane];
            float p3 = red2[s & 1][6][lane] + red2[s & 1][7][lane];
            float p4 = red2[s & 1][8][lane] + red2[s & 1][9][lane];
            float p5 = red2[s & 1][10][lane] + red2[s & 1][11][lane];
            float p6 = red2[s & 1][12][lane] + red2[s & 1][13][lane];
            float p7 = red2[s & 1][14][lane] + red2[s & 1][15][lane];
            float sum = pg + (((p0 + p1) + (p2 + p3)) + ((p4 + p5) + (p6 + p7)));
            float act = (eg == 2) ? tanh_fast(sum) : sigmoid_fast(sum);
            // lanes 0..7 (gate i) gather f (lane+8), g (lane+16), o (lane+24)
            float f_ = __shfl_down_sync(0xFFFFFFFFu, act, 8);
            float g_ = __shfl_down_sync(0xFFFFFFFFu, act, 16);
            float o_ = __shfl_down_sync(0xFFFFFFFFu, act, 24);
            float h = 0.f;
            if (eg == 0) {
                c = fmaf(f_, c, act * g_);
                h = o_ * tanh_fast(c);
            }
            // pair-pack: even lane j grabs h[j+1] from lane j+1
            float hodd = __shfl_down_sync(0xFFFFFFFFu, h, 1);
            if (eg == 0) {
                if ((ej & 1) == 0) {
                    ull pkt = pack2(h, hodd);
                    ull* dst = g_hpk + (size_t)(s + 1) * NPKT + (b << 2) + (ej >> 1);
                    asm volatile("st.global.cg.u64 [%0], %1;" :: "l"(dst), "l"(pkt));
                }
                if (s == T_STEPS - 1) { out[ejg] = h; out[H_DIM + ejg] = c; }
            }
        }
        // no end-of-step barrier: per-step buffers + sentinels gate reads
    }
}

// ---------------- launcher ---------------------------------------------------
extern "C" void kernel_launch(void* const* d_in, const int* in_sizes, int n_in,
                              void* d_out, int out_size) {
    const int*   tokens = (const int*)d_in[0];
    const float* emb    = (const float*)d_in[1];
    const float* Wih    = (const float*)d_in[2];
    const float* Whh    = (const float*)d_in[3];
    const float* bih    = (const float*)d_in[4];
    const float* bhh    = (const float*)d_in[5];
    float* out = (float*)d_out;

    init_kernel<<<(int)(((size_t)(T_STEPS + 1) * NPKT + 1023) / 1024), 1024>>>();

    dim3 ggrid(G_DIM / 128, T_STEPS / 128);  // 32 x 16
    gemm_gx<<<ggrid, 256>>>(tokens, emb, Wih, bih, bhh);

    lstm_scan<<<NCTA, 512>>>(Whh, out);
}

// round 16
// speedup vs baseline: 3.0128x; 3.0128x over previous
#include <cuda_runtime.h>
#include <cuda_bf16.h>
#include <math.h>

// Problem constants
#define T_STEPS 2048
#define H_DIM   1024
#define G_DIM   4096   // 4*H
#define NCTA    128    // <= SM count -> co-resident (required for dataflow scan)
#define NPKT    512    // h packets per step (2 h values per 8B packet)
#define SENT32  0x7FC00000u   // NaN bits: never produced by finite LSTM math

typedef unsigned long long ull;

// ---------------- device scratch (static: no allocation allowed) ------------
__device__ float g_gx[(size_t)T_STEPS * G_DIM];       // 32 MB gate inputs
// per-step pair-packed h: packet p of step s = {h[2p], h[2p+1]} bits.
// Sentinel NaN means "not yet written" (8B store is atomic).
__device__ ull g_hpk[(size_t)(T_STEPS + 1) * NPKT];

// packed fp32x2 FMA (Blackwell FFMA2 — only reachable via PTX)
__device__ __forceinline__ ull fma2(ull a, ull b, ull c) {
    ull d;
    asm("fma.rn.f32x2 %0, %1, %2, %3;" : "=l"(d) : "l"(a), "l"(b), "l"(c));
    return d;
}
__device__ __forceinline__ ull pack2(float x, float y) {
    ull d;
    asm("mov.b64 %0, {%1, %2};" : "=l"(d) : "f"(x), "f"(y));
    return d;
}

// fast activations (validated R5/R11/R12)
__device__ __forceinline__ float sigmoid_fast(float x) {
    return 1.f / (1.f + __expf(-x));
}
__device__ __forceinline__ float tanh_fast(float x) {
    return 2.f / (1.f + __expf(-2.f * x)) - 1.f;
}

// ---------------- init: sentinel everywhere, h0 = 0 --------------------------
__global__ void init_kernel() {
    size_t i = (size_t)blockIdx.x * blockDim.x + threadIdx.x;
    size_t n = (size_t)(T_STEPS + 1) * NPKT;
    if (i < n) {
        g_hpk[i] = (i < NPKT) ? 0ull
                              : (((ull)SENT32 << 32) | (ull)SENT32);
    }
}

// ---------------- GEMM: gx[t][r] = dot(emb[tok[t]], W_ih[r]) + b ------------
// f32x2-packed inner loop + register double-buffering (prefetch tile kt+16
// while tile kt computes). No divergent barriers; verified race-free.
__global__ void __launch_bounds__(256) gemm_gx(
    const int* __restrict__ tokens, const float* __restrict__ emb,
    const float* __restrict__ Wih,  const float* __restrict__ bih,
    const float* __restrict__ bhh)
{
    __shared__ float As[16][128];
    __shared__ float Bs[16][128];
    __shared__ int   tok[128];

    const int tid = threadIdx.x;
    const int n0  = blockIdx.x * 128;
    const int m0  = blockIdx.y * 128;

    if (tid < 128) tok[tid] = tokens[m0 + tid];
    __syncthreads();

    const int trow = tid >> 4;
    const int tcol = tid & 15;
    const int lm   = tid >> 2;
    const int lk   = (tid & 3) << 2;
    const int m1   = lm;        // loader row, first half
    const int m2   = lm + 64;   // loader row, second half

    ull acc2[8][4];
#pragma unroll
    for (int i = 0; i < 8; ++i)
#pragma unroll
        for (int jp = 0; jp < 4; ++jp) acc2[i][jp] = 0ull;

    // prologue: fetch tile 0 into regs, stage to smem
    float4 va1 = *reinterpret_cast<const float4*>(emb + (size_t)tok[m1] * H_DIM + lk);
    float4 va2 = *reinterpret_cast<const float4*>(emb + (size_t)tok[m2] * H_DIM + lk);
    float4 vb1 = *reinterpret_cast<const float4*>(Wih + (size_t)(n0 + m1) * H_DIM + lk);
    float4 vb2 = *reinterpret_cast<const float4*>(Wih + (size_t)(n0 + m2) * H_DIM + lk);
    As[lk + 0][m1] = va1.x; As[lk + 1][m1] = va1.y; As[lk + 2][m1] = va1.z; As[lk + 3][m1] = va1.w;
    As[lk + 0][m2] = va2.x; As[lk + 1][m2] = va2.y; As[lk + 2][m2] = va2.z; As[lk + 3][m2] = va2.w;
    Bs[lk + 0][m1] = vb1.x; Bs[lk + 1][m1] = vb1.y; Bs[lk + 2][m1] = vb1.z; Bs[lk + 3][m1] = vb1.w;
    Bs[lk + 0][m2] = vb2.x; Bs[lk + 1][m2] = vb2.y; Bs[lk + 2][m2] = vb2.z; Bs[lk + 3][m2] = vb2.w;
    __syncthreads();

    for (int kt = 0; kt < H_DIM; kt += 16) {
        const bool more = (kt + 16) < H_DIM;
        if (more) {
            const int kn = kt + 16 + lk;
            va1 = *reinterpret_cast<const float4*>(emb + (size_t)tok[m1] * H_DIM + kn);
            va2 = *reinterpret_cast<const float4*>(emb + (size_t)tok[m2] * H_DIM + kn);
            vb1 = *reinterpret_cast<const float4*>(Wih + (size_t)(n0 + m1) * H_DIM + kn);
            vb2 = *reinterpret_cast<const float4*>(Wih + (size_t)(n0 + m2) * H_DIM + kn);
        }

#pragma unroll
        for (int kk = 0; kk < 16; ++kk) {
            float a[8];
            float4 a0 = *reinterpret_cast<const float4*>(&As[kk][trow * 8]);
            float4 a1 = *reinterpret_cast<const float4*>(&As[kk][trow * 8 + 4]);
            a[0]=a0.x; a[1]=a0.y; a[2]=a0.z; a[3]=a0.w;
            a[4]=a1.x; a[5]=a1.y; a[6]=a1.z; a[7]=a1.w;
            const ull* bp = reinterpret_cast<const ull*>(&Bs[kk][tcol * 8]);
            ull b2[4] = {bp[0], bp[1], bp[2], bp[3]};
#pragma unroll
            for (int i = 0; i < 8; ++i) {
                ull ai = pack2(a[i], a[i]);
#pragma unroll
                for (int jp = 0; jp < 4; ++jp)
                    acc2[i][jp] = fma2(ai, b2[jp], acc2[i][jp]);
            }
        }

        if (more) {
            __syncthreads();
            As[lk + 0][m1] = va1.x; As[lk + 1][m1] = va1.y; As[lk + 2][m1] = va1.z; As[lk + 3][m1] = va1.w;
            As[lk + 0][m2] = va2.x; As[lk + 1][m2] = va2.y; As[lk + 2][m2] = va2.z; As[lk + 3][m2] = va2.w;
            Bs[lk + 0][m1] = vb1.x; Bs[lk + 1][m1] = vb1.y; Bs[lk + 2][m1] = vb1.z; Bs[lk + 3][m1] = vb1.w;
            Bs[lk + 0][m2] = vb2.x; Bs[lk + 1][m2] = vb2.y; Bs[lk + 2][m2] = vb2.z; Bs[lk + 3][m2] = vb2.w;
            __syncthreads();
        }
    }

    float2 bias[4];
#pragma unroll
    for (int jp = 0; jp < 4; ++jp) {
        const int n = n0 + tcol * 8 + jp * 2;
        bias[jp].x = bih[n]     + bhh[n];
        bias[jp].y = bih[n + 1] + bhh[n + 1];
    }
#pragma unroll
    for (int i = 0; i < 8; ++i) {
        const int m = m0 + trow * 8 + i;
        float2* orow = reinterpret_cast<float2*>(
            g_gx + (size_t)m * G_DIM + n0 + tcol * 8);
#pragma unroll
        for (int jp = 0; jp < 4; ++jp) {
            float2 f = *reinterpret_cast<float2*>(&acc2[i][jp]);
            f.x += bias[jp].x;
            f.y += bias[jp].y;
            orow[jp] = f;
        }
    }
}

// ---------------- persistent LSTM scan (pair-packed sentinel dataflow) -------
// EXACT R12 scan (proven 3534us): single scalar ld.cg.u64 spin + nanosleep.
// One added safety: publish sanitizes packet halves so an accidental NaN can
// never alias the sentinel (turns a would-be hang into a visible rel_err).
__global__ void __launch_bounds__(512, 1) lstm_scan(
    const float* __restrict__ Whh, float* __restrict__ out)
{
    const int tid  = threadIdx.x;
    const int b    = blockIdx.x;
    const int gate = tid >> 7;        // 0..3
    const int t    = tid & 127;       // k-slot
    const int k0   = t << 3;          // 0..1016
    const int lane = tid & 31;
    const int wig  = (tid >> 5) & 3;  // warp within gate group

    // W_hh slice into registers as f32x2 pairs: w2[j][pair]
    ull w2[8][4];
#pragma unroll
    for (int j = 0; j < 8; ++j) {
        const ull* wr = reinterpret_cast<const ull*>(
            Whh + (size_t)(gate * H_DIM + (b << 3) + j) * H_DIM + k0);
#pragma unroll
        for (int p = 0; p < 4; ++p) w2[j][p] = wr[p];
    }

    __shared__ float hs[H_DIM];
    __shared__ float red[4][4][9];    // [gate][warp-in-gate][j], padded

    // epilogue mapping (warp 0): lane = 4*j + g
    const int ej = lane >> 2;         // row 0..7
    const int eg = lane & 3;          // gate 0..3
    const int ejg = (b << 3) + ej;    // global j
    float c = 0.f;                    // cell state lives in lanes 4j (eg==0)

#pragma unroll 1
    for (int s = 0; s < T_STEPS; ++s) {
        // warp 0 prefetches gx for its gate/row (independent of h)
        float pg = 0.f;
        if (tid < 32) {
            pg = __ldg(g_gx + (size_t)s * G_DIM + eg * H_DIM + ejg);
        }

        // single scalar spin: one packet (= 2 h values) per thread
        {
            const ull* src = g_hpk + (size_t)s * NPKT + tid;
            ull p;
            for (;;) {
                asm volatile("ld.global.cg.u64 %0, [%1];"
                             : "=l"(p) : "l"(src));
                if (((unsigned)p != SENT32) &
                    ((unsigned)(p >> 32) != SENT32)) break;
                __nanosleep(24);
            }
            hs[tid * 2]     = __uint_as_float((unsigned)p);
            hs[tid * 2 + 1] = __uint_as_float((unsigned)(p >> 32));
        }
        __syncthreads();

        // h pairs for my k range
        ull h2[4];
        {
            const ull* hp = reinterpret_cast<const ull*>(hs + k0);
#pragma unroll
            for (int p = 0; p < 4; ++p) h2[p] = hp[p];
        }

        // 8 rows x 4 packed FMAs
        ull acc2[8];
#pragma unroll
        for (int j = 0; j < 8; ++j) {
            ull a = 0;
#pragma unroll
            for (int p = 0; p < 4; ++p) a = fma2(w2[j][p], h2[p], a);
            acc2[j] = a;
        }
        float acc[8];
#pragma unroll
        for (int j = 0; j < 8; ++j) {
            float2 f = *reinterpret_cast<float2*>(&acc2[j]);
            acc[j] = f.x + f.y;
        }

        // row-folding butterfly reduction: 16 shfls total
#pragma unroll
        for (int j = 0; j < 8; ++j)
            acc[j] += __shfl_xor_sync(0xFFFFFFFFu, acc[j], 16);
        float b4[4];
#pragma unroll
        for (int j = 0; j < 4; ++j) {
            b4[j] = (lane & 16) ? acc[j + 4] : acc[j];
            b4[j] += __shfl_xor_sync(0xFFFFFFFFu, b4[j], 8);
        }
        float b2[2];
#pragma unroll
        for (int j = 0; j < 2; ++j) {
            b2[j] = (lane & 8) ? b4[j + 2] : b4[j];
            b2[j] += __shfl_xor_sync(0xFFFFFFFFu, b2[j], 4);
        }
        float b1 = (lane & 4) ? b2[1] : b2[0];
        b1 += __shfl_xor_sync(0xFFFFFFFFu, b1, 2);
        b1 += __shfl_xor_sync(0xFFFFFFFFu, b1, 1);
        if ((lane & 3) == 0) red[gate][wig][(lane >> 2) & 7] = b1;
        __syncthreads();

        // parallel epilogue: warp 0, lane 4j+g handles gate g of row j
        if (tid < 32) {
            float sum = pg + red[eg][0][ej] + red[eg][1][ej]
                           + red[eg][2][ej] + red[eg][3][ej];
            float act = (eg == 2) ? tanh_fast(sum) : sigmoid_fast(sum);
            float f_ = __shfl_down_sync(0xFFFFFFFFu, act, 1);
            float g_ = __shfl_down_sync(0xFFFFFFFFu, act, 2);
            float o_ = __shfl_down_sync(0xFFFFFFFFu, act, 3);
            float h = 0.f;
            if (eg == 0) {
                c = fmaf(f_, c, act * g_);
                h = o_ * tanh_fast(c);
                if (s == T_STEPS - 1) { out[ejg] = h; out[H_DIM + ejg] = c; }
            }
            // pair-pack: lane 4j (j even) grabs h[j+1] from lane 4j+4
            float hodd = __shfl_down_sync(0xFFFFFFFFu, h, 4);
            if ((eg == 0) && ((ej & 1) == 0)) {
                unsigned lo = __float_as_uint(h);
                unsigned hi = __float_as_uint(hodd);
                // sanitize: finite h never matches; an accidental NaN gets one
                // bit flipped instead of aliasing the sentinel (no-hang rule)
                if (lo == SENT32) lo ^= 1u;
                if (hi == SENT32) hi ^= 1u;
                ull pkt = (ull)lo | ((ull)hi << 32);
                ull* dst = g_hpk + (size_t)(s + 1) * NPKT + (b << 2) + (ej >> 1);
                asm volatile("st.global.cg.u64 [%0], %1;" :: "l"(dst), "l"(pkt));
            }
        }
        // no end-of-step barrier: per-step buffers + sentinels gate reads
    }
}

// ---------------- launcher ---------------------------------------------------
extern "C" void kernel_launch(void* const* d_in, const int* in_sizes, int n_in,
                              void* d_out, int out_size) {
    const int*   tokens = (const int*)d_in[0];
    const float* emb    = (const float*)d_in[1];
    const float* Wih    = (const float*)d_in[2];
    const float* Whh    = (const float*)d_in[3];
    const float* bih    = (const float*)d_in[4];
    const float* bhh    = (const float*)d_in[5];
    float* out = (float*)d_out;

    init_kernel<<<(int)(((size_t)(T_STEPS + 1) * NPKT + 1023) / 1024), 1024>>>();

    dim3 ggrid(G_DIM / 128, T_STEPS / 128);  // 32 x 16
    gemm_gx<<<ggrid, 256>>>(tokens, emb, Wih, bih, bhh);

    lstm_scan<<<NCTA, 512>>>(Whh, out);
}